// round 2
// baseline (speedup 1.0000x reference)
#include <cuda_runtime.h>
#include <cstdint>
#include <cstddef>

#define SEQ 1024
#define BATCH 256
#define IN_DIM 131
#define HID 256
#define OUT_DIM 131
#define T_STEPS 1023
#define MROWS (T_STEPS*BATCH)   // 261888

// -------------------- scratch (static device arrays; no allocs) --------------------
__device__ float g_B1[(size_t)T_STEPS*BATCH*HID];
__device__ float g_B2[(size_t)T_STEPS*BATCH*HID];
__device__ float g_B3[(size_t)T_STEPS*BATCH*HID];
__device__ float g_decin[(size_t)T_STEPS*BATCH*IN_DIM];
__device__ float g_hn0[BATCH*HID];
__device__ float g_hn1[BATCH*HID];

// -------------------- helpers --------------------
__device__ __forceinline__ uint32_t smem_u32(const void* p) {
    return (uint32_t)__cvta_generic_to_shared(p);
}
__device__ __forceinline__ uint32_t my_ctarank() {
    uint32_t r; asm("mov.u32 %0, %%cluster_ctarank;" : "=r"(r)); return r;
}
__device__ __forceinline__ void cluster_sync_() {
    asm volatile("barrier.cluster.arrive.aligned;\n\t"
                 "barrier.cluster.wait.aligned;" ::: "memory");
}
__device__ __forceinline__ void st_shared_remote(uint32_t laddr, uint32_t peer, float v) {
    uint32_t raddr;
    asm volatile("mapa.shared::cluster.u32 %0, %1, %2;" : "=r"(raddr) : "r"(laddr), "r"(peer));
    asm volatile("st.shared::cluster.f32 [%0], %1;" :: "r"(raddr), "f"(v) : "memory");
}

// -------------------- recurrence: h_t = tanh(Z_t + h_{t-1} @ Whh^T) --------------------
// 2-CTA cluster; each CTA holds 128 rows of Whh transposed in SMEM (128KB).
// BB=8 batch rows per cluster. Thread t: jp=t&63 (2 j outputs), ks=t>>6 (64-k slice).
// Cross-slice reduction via SMEM partials; hidden halves exchanged via DSMEM.
struct RArgs {
    const float* Z;       // [T, BATCH, HID] pre-projected input (incl. both biases)
    float*       seqOut;  // nullable
    const float* W;       // Whh [HID, HID]
    const float* hInit;   // nullable -> zeros; [BATCH, HID]
    float*       hFinal;  // nullable
};

#define RBB 8
#define RECUR_SMEM ((128*HID + 2*RBB*HID + 4*RBB*128)*4)   // 163840 bytes

__global__ void __launch_bounds__(256,1) __cluster_dims__(2,1,1)
recur_kernel(RArgs a0, RArgs a1, int nClustA)
{
    extern __shared__ float smem[];
    float* sW = smem;                    // 128*256
    float* sH = sW + 128*HID;            // 2 * RBB * 256 (double buffer)
    float* sP = sH + 2*RBB*HID;          // 4 * RBB * 128 partials

    const int tid = threadIdx.x;
    const uint32_t rank = my_ctarank();
    const int cid = (int)(blockIdx.x >> 1);
    const bool isA = (cid < nClustA);
    RArgs A = isA ? a0 : a1;
    const int batch0 = (isA ? cid : (cid - nClustA)) * RBB;

    // Load weight slice transposed: sW[k*128 + j] = W[(rank*128+j)*HID + k]
    for (int idx = tid; idx < 128*HID; idx += 256) {
        int j = idx >> 8;          // 0..127
        int k = idx & 255;         // 0..255
        sW[k*128 + j] = A.W[((size_t)(rank*128 + j))*HID + k];
    }
    // Init hidden (buffer 0) — full 256-wide replica in both CTAs
    for (int idx = tid; idx < RBB*HID; idx += 256)
        sH[idx] = A.hInit ? A.hInit[(size_t)batch0*HID + idx] : 0.f;
    __syncthreads();
    cluster_sync_();

    const int jp = tid & 63;
    const int ks = tid >> 6;
    const int kbase = ks*64;

    for (int t = 0; t < T_STEPS; ++t) {
        const float* hc = sH + (t & 1)*RBB*HID;
        float*       hn = sH + ((t+1) & 1)*RBB*HID;

        // Prefetch this thread's epilogue Z values
        float zreg[RBB/2];
        const float* Zt = A.Z + ((size_t)t*BATCH + batch0)*HID;
        #pragma unroll
        for (int i = 0; i < RBB/2; i++) {
            int o = tid + i*256;               // 0..1023
            int b = o >> 7, jj = o & 127;
            zreg[i] = Zt[b*HID + (int)rank*128 + jj];
        }

        // Partial matvec: 64-k slice, 2 j's, all RBB batch rows
        float2 acc[RBB];
        #pragma unroll
        for (int b = 0; b < RBB; b++) { acc[b].x = 0.f; acc[b].y = 0.f; }

        #pragma unroll 1
        for (int k4 = kbase; k4 < kbase + 64; k4 += 4) {
            float4 hv[RBB];
            #pragma unroll
            for (int b = 0; b < RBB; b++)
                hv[b] = *(const float4*)&hc[b*HID + k4];     // warp-uniform -> broadcast
            #pragma unroll
            for (int u = 0; u < 4; u++) {
                float2 w = *(const float2*)&sW[(k4+u)*128 + 2*jp];
                #pragma unroll
                for (int b = 0; b < RBB; b++) {
                    float hvu = (u==0)?hv[b].x:(u==1)?hv[b].y:(u==2)?hv[b].z:hv[b].w;
                    acc[b].x = fmaf(w.x, hvu, acc[b].x);
                    acc[b].y = fmaf(w.y, hvu, acc[b].y);
                }
            }
        }
        #pragma unroll
        for (int b = 0; b < RBB; b++)
            ((float2*)sP)[(ks*RBB + b)*64 + jp] = acc[b];
        __syncthreads();

        // Epilogue: reduce 4 slice-partials, add Z, tanh, publish local+remote
        #pragma unroll
        for (int i = 0; i < RBB/2; i++) {
            int o = tid + i*256;
            int b = o >> 7, jj = o & 127;
            float s = zreg[i];
            #pragma unroll
            for (int p = 0; p < 4; p++)
                s += sP[(p*RBB + b)*128 + jj];
            float y = tanhf(s);
            float* dst = &hn[b*HID + (int)rank*128 + jj];
            *dst = y;
            st_shared_remote(smem_u32(dst), rank ^ 1u, y);
            if (A.seqOut)
                A.seqOut[((size_t)t*BATCH + batch0 + b)*HID + (int)rank*128 + jj] = y;
            if (A.hFinal && t == T_STEPS-1)
                A.hFinal[(size_t)(batch0 + b)*HID + (int)rank*128 + jj] = y;
        }
        cluster_sync_();
    }
}

// -------------------- GEMM: C[M,N] = A[M,K] @ W[N,K]^T + b1 (+ b2) --------------------
// 128x128 tile, 256 threads, 8x8 per-thread microtile, k-block = 8.
__global__ void __launch_bounds__(256) gemm_kernel(
    const float* __restrict__ A, const float* __restrict__ W,
    const float* __restrict__ b1, const float* __restrict__ b2,
    float* __restrict__ C, int M, int N, int K)
{
    __shared__ float sA[8*140];
    __shared__ float sB[8*140];
    const int tid = threadIdx.x;
    const int m0 = blockIdx.x * 128;
    const int n0 = blockIdx.y * 128;
    const int tx = tid & 15, ty = tid >> 4;
    float acc[8][8];
    #pragma unroll
    for (int i = 0; i < 8; i++)
        #pragma unroll
        for (int j = 0; j < 8; j++) acc[i][j] = 0.f;

    for (int k0 = 0; k0 < K; k0 += 8) {
        #pragma unroll
        for (int i = 0; i < 4; i++) {
            int lin = tid + i*256;
            int m = lin >> 3, kk = lin & 7;
            float v = 0.f;
            if (k0 + kk < K) v = A[(size_t)(m0+m)*K + k0+kk];
            sA[kk*140 + m] = v;
        }
        #pragma unroll
        for (int i = 0; i < 4; i++) {
            int lin = tid + i*256;
            int n = lin >> 3, kk = lin & 7;
            float v = 0.f;
            if ((n0+n) < N && (k0+kk) < K) v = W[(size_t)(n0+n)*K + k0+kk];
            sB[kk*140 + n] = v;
        }
        __syncthreads();
        #pragma unroll
        for (int kk = 0; kk < 8; kk++) {
            float a[8], w[8];
            *(float4*)&a[0] = *(const float4*)&sA[kk*140 + ty*8];
            *(float4*)&a[4] = *(const float4*)&sA[kk*140 + ty*8 + 4];
            *(float4*)&w[0] = *(const float4*)&sB[kk*140 + tx*8];
            *(float4*)&w[4] = *(const float4*)&sB[kk*140 + tx*8 + 4];
            #pragma unroll
            for (int i = 0; i < 8; i++)
                #pragma unroll
                for (int j = 0; j < 8; j++)
                    acc[i][j] = fmaf(a[i], w[j], acc[i][j]);
        }
        __syncthreads();
    }
    #pragma unroll
    for (int i = 0; i < 8; i++) {
        int m = m0 + ty*8 + i;
        #pragma unroll
        for (int j = 0; j < 8; j++) {
            int n = n0 + tx*8 + j;
            if (n < N) {
                float bias = b1[n] + (b2 ? b2[n] : 0.f);
                C[(size_t)m*N + n] = acc[i][j] + bias;
            }
        }
    }
}

// -------------------- dec_in = concat(X[-1], Y[:T_out-1]) --------------------
__global__ void assemble_decin(const float* __restrict__ X, const float* __restrict__ Y,
                               float* __restrict__ out) {
    const size_t total = (size_t)T_STEPS*BATCH*IN_DIM;
    const size_t slice = (size_t)BATCH*IN_DIM;
    for (size_t i = (size_t)blockIdx.x*blockDim.x + threadIdx.x; i < total;
         i += (size_t)gridDim.x*blockDim.x)
        out[i] = (i < slice) ? X[(size_t)(SEQ-1)*slice + i] : Y[i - slice];
}

// -------------------- log_softmax in place; one warp per row of 131 --------------------
__global__ void __launch_bounds__(256) logsoftmax_kernel(float* __restrict__ out, int rows) {
    int row = blockIdx.x*8 + (threadIdx.x >> 5);
    int lane = threadIdx.x & 31;
    if (row >= rows) return;
    float* p = out + (size_t)row*OUT_DIM;
    float v[5];
    float mx = -1e30f;
    #pragma unroll
    for (int i = 0; i < 5; i++) {
        int idx = lane + i*32;
        v[i] = (idx < OUT_DIM) ? p[idx] : -1e30f;
        mx = fmaxf(mx, v[i]);
    }
    #pragma unroll
    for (int o = 16; o > 0; o >>= 1)
        mx = fmaxf(mx, __shfl_xor_sync(0xffffffffu, mx, o));
    float s = 0.f;
    #pragma unroll
    for (int i = 0; i < 5; i++) {
        int idx = lane + i*32;
        if (idx < OUT_DIM) s += expf(v[i] - mx);
    }
    #pragma unroll
    for (int o = 16; o > 0; o >>= 1)
        s += __shfl_xor_sync(0xffffffffu, s, o);
    float lse = mx + logf(s);
    #pragma unroll
    for (int i = 0; i < 5; i++) {
        int idx = lane + i*32;
        if (idx < OUT_DIM) p[idx] = v[i] - lse;
    }
}

// -------------------- driver --------------------
extern "C" void kernel_launch(void* const* d_in, const int* in_sizes, int n_in,
                              void* d_out, int out_size) {
    const float* X        = (const float*)d_in[0];
    const float* Y        = (const float*)d_in[1];
    const float* eWih0    = (const float*)d_in[2];
    const float* eWhh0    = (const float*)d_in[3];
    const float* ebih0    = (const float*)d_in[4];
    const float* ebhh0    = (const float*)d_in[5];
    const float* eWih1    = (const float*)d_in[6];
    const float* eWhh1    = (const float*)d_in[7];
    const float* ebih1    = (const float*)d_in[8];
    const float* ebhh1    = (const float*)d_in[9];
    const float* dWih0    = (const float*)d_in[10];
    const float* dWhh0    = (const float*)d_in[11];
    const float* dbih0    = (const float*)d_in[12];
    const float* dbhh0    = (const float*)d_in[13];
    const float* dWih1    = (const float*)d_in[14];
    const float* dWhh1    = (const float*)d_in[15];
    const float* dbih1    = (const float*)d_in[16];
    const float* dbhh1    = (const float*)d_in[17];
    const float* lin_W    = (const float*)d_in[18];
    const float* lin_b    = (const float*)d_in[19];
    float* out = (float*)d_out;

    float *B1, *B2, *B3, *decin, *hn0, *hn1;
    cudaGetSymbolAddress((void**)&B1,    g_B1);
    cudaGetSymbolAddress((void**)&B2,    g_B2);
    cudaGetSymbolAddress((void**)&B3,    g_B3);
    cudaGetSymbolAddress((void**)&decin, g_decin);
    cudaGetSymbolAddress((void**)&hn0,   g_hn0);
    cudaGetSymbolAddress((void**)&hn1,   g_hn1);

    cudaFuncSetAttribute((const void*)recur_kernel,
                         cudaFuncAttributeMaxDynamicSharedMemorySize, RECUR_SMEM);

    const dim3 gH(MROWS/128, HID/128);              // N=256
    const dim3 gO(MROWS/128, (OUT_DIM+127)/128);    // N=131

    // 1) Z_enc0 = X[:-1] @ eWih0^T + ebih0 + ebhh0  -> B1
    gemm_kernel<<<gH, 256>>>(X, eWih0, ebih0, ebhh0, B1, MROWS, HID, IN_DIM);
    // 2) dec_in = concat(X[-1], Y[:-1])
    assemble_decin<<<2048, 256>>>(X, Y, decin);
    // 3) Z_dec0 = dec_in @ dWih0^T + dbih0 + dbhh0 -> B3
    gemm_kernel<<<gH, 256>>>(decin, dWih0, dbih0, dbhh0, B3, MROWS, HID, IN_DIM);

    // 4) encoder layer0 recurrence: B1 -> out0 (B2), hn0
    {
        RArgs a; a.Z = B1; a.seqOut = B2; a.W = eWhh0; a.hInit = nullptr; a.hFinal = hn0;
        recur_kernel<<<64, 256, RECUR_SMEM>>>(a, a, 32);
    }
    // 5) Z_enc1 = out0 @ eWih1^T + ebih1 + ebhh1 -> B1
    gemm_kernel<<<gH, 256>>>(B2, eWih1, ebih1, ebhh1, B1, MROWS, HID, HID);
    // 6) encoder layer1 (-> hn1) and decoder layer0 (-> out_d0 in B2) concurrently
    {
        RArgs a0; a0.Z = B1; a0.seqOut = nullptr; a0.W = eWhh1; a0.hInit = nullptr; a0.hFinal = hn1;
        RArgs a1; a1.Z = B3; a1.seqOut = B2;      a1.W = dWhh0; a1.hInit = hn0;     a1.hFinal = nullptr;
        recur_kernel<<<128, 256, RECUR_SMEM>>>(a0, a1, 32);
    }
    // 7) Z_dec1 = out_d0 @ dWih1^T + dbih1 + dbhh1 -> B3
    gemm_kernel<<<gH, 256>>>(B2, dWih1, dbih1, dbhh1, B3, MROWS, HID, HID);
    // 8) decoder layer1 recurrence: B3 -> out_d1 (B2), init hn1
    {
        RArgs a; a.Z = B3; a.seqOut = B2; a.W = dWhh1; a.hInit = hn1; a.hFinal = nullptr;
        recur_kernel<<<64, 256, RECUR_SMEM>>>(a, a, 32);
    }
    // 9) logits = out_d1 @ lin_W^T + lin_b -> d_out
    gemm_kernel<<<gO, 256>>>(B2, lin_W, lin_b, nullptr, out, MROWS, OUT_DIM, HID);
    // 10) log_softmax in place
    logsoftmax_kernel<<<(MROWS + 7)/8, 256>>>(out, MROWS);
}

// round 3
// speedup vs baseline: 1.2379x; 1.2379x over previous
#include <cuda_runtime.h>
#include <cstdint>
#include <cstddef>

#define SEQ 1024
#define BATCH 256
#define IN_DIM 131
#define HID 256
#define OUT_DIM 131
#define T_STEPS 1023
#define MROWS (T_STEPS*BATCH)   // 261888

// -------------------- scratch (static device arrays; no allocs) --------------------
__device__ float g_B1[(size_t)T_STEPS*BATCH*HID];
__device__ float g_B2[(size_t)T_STEPS*BATCH*HID];
__device__ float g_B3[(size_t)T_STEPS*BATCH*HID];
__device__ float g_decin[(size_t)T_STEPS*BATCH*IN_DIM];
__device__ float g_hn0[BATCH*HID];
__device__ float g_hn1[BATCH*HID];

// -------------------- helpers --------------------
__device__ __forceinline__ uint32_t smem_u32(const void* p) {
    return (uint32_t)__cvta_generic_to_shared(p);
}
__device__ __forceinline__ uint32_t my_ctarank() {
    uint32_t r; asm("mov.u32 %0, %%cluster_ctarank;" : "=r"(r)); return r;
}
__device__ __forceinline__ void cluster_sync_() {
    asm volatile("barrier.cluster.arrive.aligned;\n\t"
                 "barrier.cluster.wait.aligned;" ::: "memory");
}
__device__ __forceinline__ void st_shared_remote(uint32_t laddr, uint32_t peer, float v) {
    uint32_t raddr;
    asm volatile("mapa.shared::cluster.u32 %0, %1, %2;" : "=r"(raddr) : "r"(laddr), "r"(peer));
    asm volatile("st.shared::cluster.f32 [%0], %1;" :: "r"(raddr), "f"(v) : "memory");
}
__device__ __forceinline__ void mbar_init(uint32_t addr, uint32_t count) {
    asm volatile("mbarrier.init.shared.b64 [%0], %1;" :: "r"(addr), "r"(count) : "memory");
}
__device__ __forceinline__ void mbar_arrive_local(uint32_t addr) {
    asm volatile("mbarrier.arrive.shared.b64 _, [%0];" :: "r"(addr) : "memory");
}
__device__ __forceinline__ void mbar_arrive_remote(uint32_t laddr, uint32_t peer) {
    uint32_t raddr;
    asm volatile("mapa.shared::cluster.u32 %0, %1, %2;" : "=r"(raddr) : "r"(laddr), "r"(peer));
    asm volatile("mbarrier.arrive.release.cluster.shared::cluster.b64 _, [%0];"
                 :: "r"(raddr) : "memory");
}
__device__ __forceinline__ void mbar_wait_parity_cluster(uint32_t addr, uint32_t parity) {
    asm volatile(
        "{\n\t"
        ".reg .pred P;\n\t"
        "WAIT_%=:\n\t"
        "mbarrier.try_wait.parity.acquire.cluster.shared::cta.b64 P, [%0], %1, 0x989680;\n\t"
        "@P bra.uni DONE_%=;\n\t"
        "bra.uni WAIT_%=;\n\t"
        "DONE_%=:\n\t"
        "}" :: "r"(addr), "r"(parity) : "memory");
}

// -------------------- recurrence: h_t = tanh(Z_t + h_{t-1} @ Whh^T) --------------------
// 2-CTA cluster; each CTA holds 128 rows of Whh transposed in SMEM (128KB).
// RBB batch rows per cluster. Thread t: jp=t&63 (2 j outputs), ks=t>>6 (64-k slice).
// Cross-slice reduction via SMEM partials; hidden halves exchanged via DSMEM.
// Per-step cluster sync via 512-count mbarrier (256 local + 256 remote arrivals).
struct RArgs {
    const float* Z;       // [T, BATCH, HID] pre-projected input (incl. both biases)
    float*       seqOut;  // nullable
    const float* W;       // Whh [HID, HID]
    const float* hInit;   // nullable -> zeros; [BATCH, HID]
    float*       hFinal;  // nullable
};

#define RECUR_SMEM(RBB) ((4 + 128*HID + 2*(RBB)*HID + 4*(RBB)*128)*4)

template<int RBB>
__global__ void __launch_bounds__(256,1) __cluster_dims__(2,1,1)
recur_kernel(RArgs a0, RArgs a1, int nClustA)
{
    extern __shared__ float smem[];
    // smem[0..1] hold the 8-byte mbarrier; weights start at +4 floats (16B aligned)
    float* sW = smem + 4;                // 128*256
    float* sH = sW + 128*HID;            // 2 * RBB * 256 (double buffer)
    float* sP = sH + 2*RBB*HID;          // 4 * RBB * 128 partials

    const int tid = threadIdx.x;
    const uint32_t rank = my_ctarank();
    const uint32_t peer = rank ^ 1u;
    const int cid = (int)(blockIdx.x >> 1);
    const bool isA = (cid < nClustA);
    RArgs A = isA ? a0 : a1;
    const int batch0 = (isA ? cid : (cid - nClustA)) * RBB;
    const uint32_t barAddr = smem_u32(smem);

    if (tid == 0) mbar_init(barAddr, 512);

    // Load weight slice transposed: sW[k*128 + j] = W[(rank*128+j)*HID + k]
    for (int idx = tid; idx < 128*HID; idx += 256) {
        int j = idx >> 8;          // 0..127
        int k = idx & 255;         // 0..255
        sW[k*128 + j] = A.W[((size_t)(rank*128 + j))*HID + k];
    }
    // Init hidden (buffer 0) — full 256-wide replica in both CTAs
    for (int idx = tid; idx < RBB*HID; idx += 256)
        sH[idx] = A.hInit ? A.hInit[(size_t)batch0*HID + idx] : 0.f;
    __syncthreads();
    cluster_sync_();    // barriers initialized + weights/hidden ready in both CTAs

    const int jp = tid & 63;
    const int ks = tid >> 6;
    const int kbase = ks*64;

    for (int t = 0; t < T_STEPS; ++t) {
        const float* hc = sH + (t & 1)*RBB*HID;
        float*       hn = sH + ((t+1) & 1)*RBB*HID;

        // Prefetch this thread's epilogue Z values
        float zreg[RBB/2];
        const float* Zt = A.Z + ((size_t)t*BATCH + batch0)*HID;
        #pragma unroll
        for (int i = 0; i < RBB/2; i++) {
            int o = tid + i*256;
            int b = o >> 7, jj = o & 127;
            zreg[i] = Zt[b*HID + (int)rank*128 + jj];
        }

        // Partial matvec: 64-k slice, 2 j's, all RBB batch rows
        float2 acc[RBB];
        #pragma unroll
        for (int b = 0; b < RBB; b++) { acc[b].x = 0.f; acc[b].y = 0.f; }

        #pragma unroll 1
        for (int k4 = kbase; k4 < kbase + 64; k4 += 4) {
            float4 hv[RBB];
            #pragma unroll
            for (int b = 0; b < RBB; b++)
                hv[b] = *(const float4*)&hc[b*HID + k4];     // warp-uniform -> broadcast
            #pragma unroll
            for (int u = 0; u < 4; u++) {
                float2 w = *(const float2*)&sW[(k4+u)*128 + 2*jp];
                #pragma unroll
                for (int b = 0; b < RBB; b++) {
                    float hvu = (u==0)?hv[b].x:(u==1)?hv[b].y:(u==2)?hv[b].z:hv[b].w;
                    acc[b].x = fmaf(w.x, hvu, acc[b].x);
                    acc[b].y = fmaf(w.y, hvu, acc[b].y);
                }
            }
        }
        #pragma unroll
        for (int b = 0; b < RBB; b++)
            ((float2*)sP)[(ks*RBB + b)*64 + jp] = acc[b];
        __syncthreads();

        // Epilogue: reduce 4 slice-partials, add Z, tanh, publish local+remote
        #pragma unroll
        for (int i = 0; i < RBB/2; i++) {
            int o = tid + i*256;
            int b = o >> 7, jj = o & 127;
            float s = zreg[i];
            #pragma unroll
            for (int p = 0; p < 4; p++)
                s += sP[(p*RBB + b)*128 + jj];
            float y = tanhf(s);
            float* dst = &hn[b*HID + (int)rank*128 + jj];
            *dst = y;
            st_shared_remote(smem_u32(dst), peer, y);
            if (A.seqOut)
                A.seqOut[((size_t)t*BATCH + batch0 + b)*HID + (int)rank*128 + jj] = y;
            if (A.hFinal && t == T_STEPS-1)
                A.hFinal[(size_t)(batch0 + b)*HID + (int)rank*128 + jj] = y;
        }
        // Mutual cluster step barrier: my arrivals also certify my reads of hc are done,
        // so the peer cannot overwrite buffers for step t+1 early.
        mbar_arrive_remote(barAddr, peer);
        mbar_arrive_local(barAddr);
        mbar_wait_parity_cluster(barAddr, (uint32_t)(t & 1));
    }
}

// -------------------- GEMM: C[M,N] = A[M,K] @ W[N,K]^T + b1 (+ b2) --------------------
// 128x128 tile, 256 threads, 8x8 per-thread microtile, k-block = 16.
__global__ void __launch_bounds__(256) gemm_kernel(
    const float* __restrict__ A, const float* __restrict__ W,
    const float* __restrict__ b1, const float* __restrict__ b2,
    float* __restrict__ C, int M, int N, int K)
{
    __shared__ float sA[16*136];
    __shared__ float sB[16*136];
    const int tid = threadIdx.x;
    const int m0 = blockIdx.x * 128;
    const int n0 = blockIdx.y * 128;
    const int tx = tid & 15, ty = tid >> 4;
    float acc[8][8];
    #pragma unroll
    for (int i = 0; i < 8; i++)
        #pragma unroll
        for (int j = 0; j < 8; j++) acc[i][j] = 0.f;

    for (int k0 = 0; k0 < K; k0 += 16) {
        #pragma unroll
        for (int i = 0; i < 8; i++) {
            int lin = tid + i*256;
            int m = lin >> 4, kk = lin & 15;
            float v = 0.f;
            if (k0 + kk < K) v = A[(size_t)(m0+m)*K + k0+kk];
            sA[kk*136 + m] = v;
        }
        #pragma unroll
        for (int i = 0; i < 8; i++) {
            int lin = tid + i*256;
            int n = lin >> 4, kk = lin & 15;
            float v = 0.f;
            if ((n0+n) < N && (k0+kk) < K) v = W[(size_t)(n0+n)*K + k0+kk];
            sB[kk*136 + n] = v;
        }
        __syncthreads();
        #pragma unroll
        for (int kk = 0; kk < 16; kk++) {
            float a[8], w[8];
            *(float4*)&a[0] = *(const float4*)&sA[kk*136 + ty*8];
            *(float4*)&a[4] = *(const float4*)&sA[kk*136 + ty*8 + 4];
            *(float4*)&w[0] = *(const float4*)&sB[kk*136 + tx*8];
            *(float4*)&w[4] = *(const float4*)&sB[kk*136 + tx*8 + 4];
            #pragma unroll
            for (int i = 0; i < 8; i++)
                #pragma unroll
                for (int j = 0; j < 8; j++)
                    acc[i][j] = fmaf(a[i], w[j], acc[i][j]);
        }
        __syncthreads();
    }
    #pragma unroll
    for (int i = 0; i < 8; i++) {
        int m = m0 + ty*8 + i;
        #pragma unroll
        for (int j = 0; j < 8; j++) {
            int n = n0 + tx*8 + j;
            if (n < N) {
                float bias = b1[n] + (b2 ? b2[n] : 0.f);
                C[(size_t)m*N + n] = acc[i][j] + bias;
            }
        }
    }
}

// -------------------- dec_in = concat(X[-1], Y[:T_out-1]) --------------------
__global__ void assemble_decin(const float* __restrict__ X, const float* __restrict__ Y,
                               float* __restrict__ out) {
    const size_t total = (size_t)T_STEPS*BATCH*IN_DIM;
    const size_t slice = (size_t)BATCH*IN_DIM;
    for (size_t i = (size_t)blockIdx.x*blockDim.x + threadIdx.x; i < total;
         i += (size_t)gridDim.x*blockDim.x)
        out[i] = (i < slice) ? X[(size_t)(SEQ-1)*slice + i] : Y[i - slice];
}

// -------------------- log_softmax in place; one warp per row of 131 --------------------
__global__ void __launch_bounds__(256) logsoftmax_kernel(float* __restrict__ out, int rows) {
    int row = blockIdx.x*8 + (threadIdx.x >> 5);
    int lane = threadIdx.x & 31;
    if (row >= rows) return;
    float* p = out + (size_t)row*OUT_DIM;
    float v[5];
    float mx = -1e30f;
    #pragma unroll
    for (int i = 0; i < 5; i++) {
        int idx = lane + i*32;
        v[i] = (idx < OUT_DIM) ? p[idx] : -1e30f;
        mx = fmaxf(mx, v[i]);
    }
    #pragma unroll
    for (int o = 16; o > 0; o >>= 1)
        mx = fmaxf(mx, __shfl_xor_sync(0xffffffffu, mx, o));
    float s = 0.f;
    #pragma unroll
    for (int i = 0; i < 5; i++) {
        int idx = lane + i*32;
        if (idx < OUT_DIM) s += expf(v[i] - mx);
    }
    #pragma unroll
    for (int o = 16; o > 0; o >>= 1)
        s += __shfl_xor_sync(0xffffffffu, s, o);
    float lse = mx + logf(s);
    #pragma unroll
    for (int i = 0; i < 5; i++) {
        int idx = lane + i*32;
        if (idx < OUT_DIM) p[idx] = v[i] - lse;
    }
}

// -------------------- driver --------------------
extern "C" void kernel_launch(void* const* d_in, const int* in_sizes, int n_in,
                              void* d_out, int out_size) {
    const float* X        = (const float*)d_in[0];
    const float* Y        = (const float*)d_in[1];
    const float* eWih0    = (const float*)d_in[2];
    const float* eWhh0    = (const float*)d_in[3];
    const float* ebih0    = (const float*)d_in[4];
    const float* ebhh0    = (const float*)d_in[5];
    const float* eWih1    = (const float*)d_in[6];
    const float* eWhh1    = (const float*)d_in[7];
    const float* ebih1    = (const float*)d_in[8];
    const float* ebhh1    = (const float*)d_in[9];
    const float* dWih0    = (const float*)d_in[10];
    const float* dWhh0    = (const float*)d_in[11];
    const float* dbih0    = (const float*)d_in[12];
    const float* dbhh0    = (const float*)d_in[13];
    const float* dWih1    = (const float*)d_in[14];
    const float* dWhh1    = (const float*)d_in[15];
    const float* dbih1    = (const float*)d_in[16];
    const float* dbhh1    = (const float*)d_in[17];
    const float* lin_W    = (const float*)d_in[18];
    const float* lin_b    = (const float*)d_in[19];
    float* out = (float*)d_out;

    float *B1, *B2, *B3, *decin, *hn0, *hn1;
    cudaGetSymbolAddress((void**)&B1,    g_B1);
    cudaGetSymbolAddress((void**)&B2,    g_B2);
    cudaGetSymbolAddress((void**)&B3,    g_B3);
    cudaGetSymbolAddress((void**)&decin, g_decin);
    cudaGetSymbolAddress((void**)&hn0,   g_hn0);
    cudaGetSymbolAddress((void**)&hn1,   g_hn1);

    cudaFuncSetAttribute((const void*)recur_kernel<4>,
                         cudaFuncAttributeMaxDynamicSharedMemorySize, RECUR_SMEM(4));
    cudaFuncSetAttribute((const void*)recur_kernel<8>,
                         cudaFuncAttributeMaxDynamicSharedMemorySize, RECUR_SMEM(8));

    const dim3 gH(MROWS/128, HID/128);              // N=256
    const dim3 gO(MROWS/128, (OUT_DIM+127)/128);    // N=131

    // 1) Z_enc0 = X[:-1] @ eWih0^T + ebih0 + ebhh0  -> B1
    gemm_kernel<<<gH, 256>>>(X, eWih0, ebih0, ebhh0, B1, MROWS, HID, IN_DIM);
    // 2) dec_in = concat(X[-1], Y[:-1])
    assemble_decin<<<2048, 256>>>(X, Y, decin);
    // 3) Z_dec0 = dec_in @ dWih0^T + dbih0 + dbhh0 -> B3
    gemm_kernel<<<gH, 256>>>(decin, dWih0, dbih0, dbhh0, B3, MROWS, HID, IN_DIM);

    // 4) encoder layer0 recurrence: B1 -> out0 (B2), hn0   [RBB=4 -> 128 CTAs]
    {
        RArgs a; a.Z = B1; a.seqOut = B2; a.W = eWhh0; a.hInit = nullptr; a.hFinal = hn0;
        recur_kernel<4><<<128, 256, RECUR_SMEM(4)>>>(a, a, 64);
    }
    // 5) Z_enc1 = out0 @ eWih1^T + ebih1 + ebhh1 -> B1
    gemm_kernel<<<gH, 256>>>(B2, eWih1, ebih1, ebhh1, B1, MROWS, HID, HID);
    // 6) encoder layer1 (-> hn1) and decoder layer0 (-> out_d0 in B2) concurrently [RBB=8]
    {
        RArgs a0; a0.Z = B1; a0.seqOut = nullptr; a0.W = eWhh1; a0.hInit = nullptr; a0.hFinal = hn1;
        RArgs a1; a1.Z = B3; a1.seqOut = B2;      a1.W = dWhh0; a1.hInit = hn0;     a1.hFinal = nullptr;
        recur_kernel<8><<<128, 256, RECUR_SMEM(8)>>>(a0, a1, 32);
    }
    // 7) Z_dec1 = out_d0 @ dWih1^T + dbih1 + dbhh1 -> B3
    gemm_kernel<<<gH, 256>>>(B2, dWih1, dbih1, dbhh1, B3, MROWS, HID, HID);
    // 8) decoder layer1 recurrence: B3 -> out_d1 (B2), init hn1   [RBB=4]
    {
        RArgs a; a.Z = B3; a.seqOut = B2; a.W = dWhh1; a.hInit = hn1; a.hFinal = nullptr;
        recur_kernel<4><<<128, 256, RECUR_SMEM(4)>>>(a, a, 64);
    }
    // 9) logits = out_d1 @ lin_W^T + lin_b -> d_out
    gemm_kernel<<<gO, 256>>>(B2, lin_W, lin_b, nullptr, out, MROWS, OUT_DIM, HID);
    // 10) log_softmax in place
    logsoftmax_kernel<<<(MROWS + 7)/8, 256>>>(out, MROWS);
}

// round 6
// speedup vs baseline: 1.4905x; 1.2041x over previous
#include <cuda_runtime.h>
#include <cuda_bf16.h>
#include <cstdint>
#include <cstddef>

#define SEQ 1024
#define BATCH 256
#define IN_DIM 131
#define HID 256
#define OUT_DIM 131
#define T_STEPS 1023
#define MROWS (T_STEPS*BATCH)   // 261888 = 128 * 2046
#define KP_IN 192               // padded K for IN_DIM=131 GEMMs

// -------------------- scratch (static device arrays; no allocs) --------------------
__device__ float          g_Zenc[(size_t)MROWS*HID];
__device__ float          g_Zdec[(size_t)MROWS*HID];
__device__ __nv_bfloat16  g_Hhi[(size_t)MROWS*HID];
__device__ __nv_bfloat16  g_Hlo[(size_t)MROWS*HID];
__device__ __nv_bfloat16  g_Xhi[(size_t)MROWS*KP_IN];
__device__ __nv_bfloat16  g_Xlo[(size_t)MROWS*KP_IN];
__device__ __nv_bfloat16  g_Dhi[(size_t)MROWS*KP_IN];
__device__ __nv_bfloat16  g_Dlo[(size_t)MROWS*KP_IN];
__device__ __nv_bfloat16  g_Wh[5*256*256];
__device__ __nv_bfloat16  g_Wl[5*256*256];
__device__ float          g_hn0[BATCH*HID];
__device__ float          g_hn1[BATCH*HID];

// -------------------- common helpers --------------------
__device__ __forceinline__ uint32_t smem_u32(const void* p) {
    return (uint32_t)__cvta_generic_to_shared(p);
}
__device__ __forceinline__ uint32_t my_ctarank() {
    uint32_t r; asm("mov.u32 %0, %%cluster_ctarank;" : "=r"(r)); return r;
}
__device__ __forceinline__ void cluster_sync_() {
    asm volatile("barrier.cluster.arrive.aligned;\n\t"
                 "barrier.cluster.wait.aligned;" ::: "memory");
}
__device__ __forceinline__ void st_shared_remote(uint32_t laddr, uint32_t peer, float v) {
    uint32_t raddr;
    asm volatile("mapa.shared::cluster.u32 %0, %1, %2;" : "=r"(raddr) : "r"(laddr), "r"(peer));
    asm volatile("st.shared::cluster.f32 [%0], %1;" :: "r"(raddr), "f"(v) : "memory");
}
__device__ __forceinline__ void mbar_init(uint32_t addr, uint32_t count) {
    asm volatile("mbarrier.init.shared.b64 [%0], %1;" :: "r"(addr), "r"(count) : "memory");
}
__device__ __forceinline__ void mbar_arrive_local(uint32_t addr) {
    asm volatile("mbarrier.arrive.shared.b64 _, [%0];" :: "r"(addr) : "memory");
}
__device__ __forceinline__ void mbar_arrive_remote(uint32_t laddr, uint32_t peer) {
    uint32_t raddr;
    asm volatile("mapa.shared::cluster.u32 %0, %1, %2;" : "=r"(raddr) : "r"(laddr), "r"(peer));
    asm volatile("mbarrier.arrive.release.cluster.shared::cluster.b64 _, [%0];"
                 :: "r"(raddr) : "memory");
}
__device__ __forceinline__ void mbar_wait_cluster(uint32_t addr, uint32_t parity) {
    asm volatile(
        "{\n\t.reg .pred P;\n\t"
        "WAIT_%=:\n\t"
        "mbarrier.try_wait.parity.acquire.cluster.shared::cta.b64 P, [%0], %1, 0x989680;\n\t"
        "@P bra.uni DONE_%=;\n\t"
        "bra.uni WAIT_%=;\n\t"
        "DONE_%=:\n\t}" :: "r"(addr), "r"(parity) : "memory");
}

// -------------------- mma.sync / ldmatrix primitives (compute_103-legal) --------------------
__device__ __forceinline__ uint32_t swz128(uint32_t off) {
    return off ^ ((off >> 3) & 0x70);
}
__device__ __forceinline__ void ldm4(uint32_t* r, uint32_t addr) {
    asm volatile("ldmatrix.sync.aligned.m8n8.x4.shared.b16 {%0,%1,%2,%3}, [%4];"
        : "=r"(r[0]), "=r"(r[1]), "=r"(r[2]), "=r"(r[3]) : "r"(addr));
}
__device__ __forceinline__ void mma16816(float* d, const uint32_t* a, uint32_t b0, uint32_t b1) {
    asm volatile("mma.sync.aligned.m16n8k16.row.col.f32.bf16.bf16.f32 "
        "{%0,%1,%2,%3}, {%4,%5,%6,%7}, {%8,%9}, {%0,%1,%2,%3};"
        : "+f"(d[0]), "+f"(d[1]), "+f"(d[2]), "+f"(d[3])
        : "r"(a[0]), "r"(a[1]), "r"(a[2]), "r"(a[3]), "r"(b0), "r"(b1));
}

// -------------------- tensor GEMM: C = [Ahi|Alo|Ahi] @ [Bhi|Bhi|Blo]^T + bias --------------------
// A: [MROWS, Kp] bf16. B: [256, Kp] bf16 padded weights. C: [MROWS, Nout] f32.
// CTA: 128x128 tile, 256 threads = 8 warps (4 m x 2 n), warp tile 32x64.
// K chunks of 64 bf16 (128B rows, SW128), double-buffered, 3 split-bf16 passes.
#define GM_SMEM (2*16384*2)     // 65536: [buf][A 16KB | B 16KB]

__global__ void __launch_bounds__(256,1)
gemm_mma(const __nv_bfloat16* __restrict__ Ahi, const __nv_bfloat16* __restrict__ Alo,
         const __nv_bfloat16* __restrict__ Bhi, const __nv_bfloat16* __restrict__ Blo,
         const float* __restrict__ b1, const float* __restrict__ b2,
         float* __restrict__ C, int Nout, int Kp)
{
    extern __shared__ char smem[];
    const uint32_t sb = smem_u32(smem);
    const int tid = threadIdx.x;
    const int lane = tid & 31, warp = tid >> 5;
    const int wm = warp & 3, wn = warp >> 2;
    const int m0 = blockIdx.x * 128;
    const int n0 = blockIdx.y * 128;

    const int kchunks = Kp >> 6;
    const int nch = 3 * kchunks;

    // staging-load index precompute (4 uint4 each for A and B)
    int lrow[4], lcol[4];
    #pragma unroll
    for (int i = 0; i < 4; i++) {
        int lin = tid + i*256;          // 0..1023
        lrow[i] = lin >> 3;             // 0..127
        lcol[i] = (lin & 7) * 16;       // byte col
    }

    // ldmatrix per-thread byte offsets (within a chunk image: row*128 + col)
    const int aidx = lane & 7;
    uint32_t aoff[2];
    #pragma unroll
    for (int mi = 0; mi < 2; mi++) {
        int r = wm*32 + mi*16 + aidx + ((lane >> 3) & 1)*8;
        aoff[mi] = (uint32_t)(r*128 + ((lane >> 4) & 1)*16);
    }
    uint32_t boff[4];
    #pragma unroll
    for (int j = 0; j < 4; j++) {
        int r = wn*64 + j*16 + aidx + ((lane >> 4) & 1)*8;
        boff[j] = (uint32_t)(r*128 + ((lane >> 3) & 1)*16);
    }

    float acc[2][8][4];
    #pragma unroll
    for (int mi = 0; mi < 2; mi++)
        #pragma unroll
        for (int ni = 0; ni < 8; ni++)
            #pragma unroll
            for (int q = 0; q < 4; q++) acc[mi][ni][q] = 0.f;

    uint4 ra[4], rb[4];
    // pass/chunk source resolution
    auto srcA = [&](int c) -> const __nv_bfloat16* {
        int pass = c / kchunks; return (pass == 1) ? Alo : Ahi;
    };
    auto srcB = [&](int c) -> const __nv_bfloat16* {
        int pass = c / kchunks; return (pass == 2) ? Blo : Bhi;
    };
    auto kcOf = [&](int c) -> int { int pass = c / kchunks; return c - pass*kchunks; };

    // preload chunk 0
    {
        const __nv_bfloat16* Ap = srcA(0);
        const __nv_bfloat16* Bp = srcB(0);
        #pragma unroll
        for (int i = 0; i < 4; i++) {
            ra[i] = *(const uint4*)((const char*)Ap + ((size_t)(m0 + lrow[i])*Kp)*2 + lcol[i]);
            rb[i] = *(const uint4*)((const char*)Bp + ((size_t)(n0 + lrow[i])*Kp)*2 + lcol[i]);
        }
        #pragma unroll
        for (int i = 0; i < 4; i++) {
            *(uint4*)(smem + swz128((uint32_t)(lrow[i]*128 + lcol[i]))) = ra[i];
            *(uint4*)(smem + 16384 + swz128((uint32_t)(lrow[i]*128 + lcol[i]))) = rb[i];
        }
    }
    __syncthreads();

    for (int c = 0; c < nch; ++c) {
        const int buf = c & 1;
        const uint32_t aB = sb + buf*32768;
        const uint32_t bB = sb + buf*32768 + 16384;

        // issue next chunk's global loads first (overlap with mma)
        if (c + 1 < nch) {
            const __nv_bfloat16* Ap = srcA(c+1);
            const __nv_bfloat16* Bp = srcB(c+1);
            const int kc = kcOf(c+1);
            #pragma unroll
            for (int i = 0; i < 4; i++) {
                ra[i] = *(const uint4*)((const char*)Ap + ((size_t)(m0 + lrow[i])*Kp)*2 + kc*128 + lcol[i]);
                rb[i] = *(const uint4*)((const char*)Bp + ((size_t)(n0 + lrow[i])*Kp)*2 + kc*128 + lcol[i]);
            }
        }

        // compute on current buffer: 4 k16 steps
        #pragma unroll
        for (int ks = 0; ks < 4; ks++) {
            uint32_t afr[2][4];
            #pragma unroll
            for (int mi = 0; mi < 2; mi++)
                ldm4(afr[mi], aB + swz128(aoff[mi] + ks*32));
            #pragma unroll
            for (int j = 0; j < 4; j++) {
                uint32_t bfr[4];
                ldm4(bfr, bB + swz128(boff[j] + ks*32));
                #pragma unroll
                for (int mi = 0; mi < 2; mi++) {
                    mma16816(acc[mi][2*j],   afr[mi], bfr[0], bfr[1]);
                    mma16816(acc[mi][2*j+1], afr[mi], bfr[2], bfr[3]);
                }
            }
        }

        // store staged data into the other buffer
        if (c + 1 < nch) {
            char* ag = smem + (buf ^ 1)*32768;
            char* bg = smem + (buf ^ 1)*32768 + 16384;
            #pragma unroll
            for (int i = 0; i < 4; i++) {
                *(uint4*)(ag + swz128((uint32_t)(lrow[i]*128 + lcol[i]))) = ra[i];
                *(uint4*)(bg + swz128((uint32_t)(lrow[i]*128 + lcol[i]))) = rb[i];
            }
        }
        __syncthreads();
    }

    // epilogue: write C + bias (mask n < Nout)
    const int er = lane >> 2, ec = (lane & 3) * 2;
    #pragma unroll
    for (int mi = 0; mi < 2; mi++) {
        #pragma unroll
        for (int ni = 0; ni < 8; ni++) {
            const int nbase = n0 + wn*64 + ni*8 + ec;
            const int mbase = m0 + wm*32 + mi*16 + er;
            #pragma unroll
            for (int half = 0; half < 2; half++) {   // rows er, er+8
                int m = mbase + half*8;
                #pragma unroll
                for (int q = 0; q < 2; q++) {        // cols ec, ec+1
                    int n = nbase + q;
                    if (n < Nout) {
                        float bias = __ldg(&b1[n]) + (b2 ? __ldg(&b2[n]) : 0.f);
                        C[(size_t)m*Nout + n] = acc[mi][ni][half*2 + q] + bias;
                    }
                }
            }
        }
    }
}

// -------------------- recurrence: h_t = tanh(Z_t + h_{t-1} @ Whh^T) --------------------
struct RArgs {
    const float*   Z;       // [T, BATCH, HID] pre-projected input (incl. both biases)
    __nv_bfloat16* outHi;   // nullable: split-bf16 sequence output
    __nv_bfloat16* outLo;
    const float*   W;       // Whh [HID, HID]
    const float*   hInit;   // nullable -> zeros
    float*         hFinal;  // nullable
};

#define RECUR_SMEM(RBB) ((4 + 128*HID + 2*(RBB)*HID + 4*(RBB)*128)*4)

template<int RBB>
__global__ void __launch_bounds__(256,1) __cluster_dims__(2,1,1)
recur_kernel(RArgs a0, RArgs a1, int nClustA)
{
    extern __shared__ float smemf[];
    float* sW = smemf + 4;
    float* sH = sW + 128*HID;
    float* sP = sH + 2*RBB*HID;

    const int tid = threadIdx.x;
    const uint32_t rank = my_ctarank();
    const uint32_t peer = rank ^ 1u;
    const int cid = (int)(blockIdx.x >> 1);
    const bool isA = (cid < nClustA);
    RArgs A = isA ? a0 : a1;
    const int batch0 = (isA ? cid : (cid - nClustA)) * RBB;
    const uint32_t barAddr = smem_u32(smemf);

    if (tid == 0) mbar_init(barAddr, 512);

    for (int idx = tid; idx < 128*HID; idx += 256) {
        int j = idx >> 8;
        int k = idx & 255;
        sW[k*128 + j] = A.W[((size_t)(rank*128 + j))*HID + k];
    }
    for (int idx = tid; idx < RBB*HID; idx += 256)
        sH[idx] = A.hInit ? A.hInit[(size_t)batch0*HID + idx] : 0.f;
    __syncthreads();
    cluster_sync_();

    const int jp = tid & 63;
    const int ks = tid >> 6;
    const int kbase = ks*64;

    for (int t = 0; t < T_STEPS; ++t) {
        const float* hc = sH + (t & 1)*RBB*HID;
        float*       hn = sH + ((t+1) & 1)*RBB*HID;

        float zreg[RBB/2];
        const float* Zt = A.Z + ((size_t)t*BATCH + batch0)*HID;
        #pragma unroll
        for (int i = 0; i < RBB/2; i++) {
            int o = tid + i*256;
            int b = o >> 7, jj = o & 127;
            zreg[i] = Zt[b*HID + (int)rank*128 + jj];
        }

        float2 acc[RBB];
        #pragma unroll
        for (int b = 0; b < RBB; b++) { acc[b].x = 0.f; acc[b].y = 0.f; }

        #pragma unroll 1
        for (int k4 = kbase; k4 < kbase + 64; k4 += 4) {
            float4 hv[RBB];
            #pragma unroll
            for (int b = 0; b < RBB; b++)
                hv[b] = *(const float4*)&hc[b*HID + k4];
            #pragma unroll
            for (int u = 0; u < 4; u++) {
                float2 w = *(const float2*)&sW[(k4+u)*128 + 2*jp];
                #pragma unroll
                for (int b = 0; b < RBB; b++) {
                    float hvu = (u==0)?hv[b].x:(u==1)?hv[b].y:(u==2)?hv[b].z:hv[b].w;
                    acc[b].x = fmaf(w.x, hvu, acc[b].x);
                    acc[b].y = fmaf(w.y, hvu, acc[b].y);
                }
            }
        }
        #pragma unroll
        for (int b = 0; b < RBB; b++)
            ((float2*)sP)[(ks*RBB + b)*64 + jp] = acc[b];
        __syncthreads();

        #pragma unroll
        for (int i = 0; i < RBB/2; i++) {
            int o = tid + i*256;
            int b = o >> 7, jj = o & 127;
            float s = zreg[i];
            #pragma unroll
            for (int p = 0; p < 4; p++)
                s += sP[(p*RBB + b)*128 + jj];
            float y = tanhf(s);
            float* dst = &hn[b*HID + (int)rank*128 + jj];
            *dst = y;
            st_shared_remote(smem_u32(dst), peer, y);
            if (A.outHi) {
                size_t gi = ((size_t)t*BATCH + batch0 + b)*HID + (int)rank*128 + jj;
                __nv_bfloat16 h = __float2bfloat16(y);
                A.outHi[gi] = h;
                A.outLo[gi] = __float2bfloat16(y - __bfloat162float(h));
            }
            if (A.hFinal && t == T_STEPS-1)
                A.hFinal[(size_t)(batch0 + b)*HID + (int)rank*128 + jj] = y;
        }
        mbar_arrive_remote(barAddr, peer);
        mbar_arrive_local(barAddr);
        mbar_wait_cluster(barAddr, (uint32_t)(t & 1));
    }
}

// -------------------- split converters --------------------
__global__ void wsplit(const float* __restrict__ W, __nv_bfloat16* __restrict__ hi,
                       __nv_bfloat16* __restrict__ lo, int Nw, int Kw, int Kp)
{
    int i = blockIdx.x*blockDim.x + threadIdx.x;
    if (i >= 256*Kp) return;
    int r = i / Kp, c = i - r*Kp;
    float v = (r < Nw && c < Kw) ? W[r*Kw + c] : 0.f;
    __nv_bfloat16 h = __float2bfloat16(v);
    hi[i] = h;
    lo[i] = __float2bfloat16(v - __bfloat162float(h));
}

__global__ void xsplit(const float* __restrict__ src, __nv_bfloat16* __restrict__ hi,
                       __nv_bfloat16* __restrict__ lo)
{
    const size_t total = (size_t)MROWS*KP_IN;
    for (size_t i = (size_t)blockIdx.x*blockDim.x + threadIdx.x; i < total;
         i += (size_t)gridDim.x*blockDim.x) {
        size_t r = i / KP_IN;
        int c = (int)(i - r*KP_IN);
        float v = (c < IN_DIM) ? src[r*IN_DIM + c] : 0.f;
        __nv_bfloat16 h = __float2bfloat16(v);
        hi[i] = h;
        lo[i] = __float2bfloat16(v - __bfloat162float(h));
    }
}

// dec_in row r: r<256 -> X[1023*256 + r], else Y[r-256]
__global__ void decsplit(const float* __restrict__ X, const float* __restrict__ Y,
                         __nv_bfloat16* __restrict__ hi, __nv_bfloat16* __restrict__ lo)
{
    const size_t total = (size_t)MROWS*KP_IN;
    for (size_t i = (size_t)blockIdx.x*blockDim.x + threadIdx.x; i < total;
         i += (size_t)gridDim.x*blockDim.x) {
        size_t r = i / KP_IN;
        int c = (int)(i - r*KP_IN);
        float v = 0.f;
        if (c < IN_DIM)
            v = (r < BATCH) ? X[((size_t)1023*BATCH + r)*IN_DIM + c]
                            : Y[(r - BATCH)*IN_DIM + c];
        __nv_bfloat16 h = __float2bfloat16(v);
        hi[i] = h;
        lo[i] = __float2bfloat16(v - __bfloat162float(h));
    }
}

// -------------------- log_softmax in place --------------------
__global__ void __launch_bounds__(256) logsoftmax_kernel(float* __restrict__ out, int rows) {
    int row = blockIdx.x*8 + (threadIdx.x >> 5);
    int lane = threadIdx.x & 31;
    if (row >= rows) return;
    float* p = out + (size_t)row*OUT_DIM;
    float v[5];
    float mx = -1e30f;
    #pragma unroll
    for (int i = 0; i < 5; i++) {
        int idx = lane + i*32;
        v[i] = (idx < OUT_DIM) ? p[idx] : -1e30f;
        mx = fmaxf(mx, v[i]);
    }
    #pragma unroll
    for (int o = 16; o > 0; o >>= 1)
        mx = fmaxf(mx, __shfl_xor_sync(0xffffffffu, mx, o));
    float s = 0.f;
    #pragma unroll
    for (int i = 0; i < 5; i++) {
        int idx = lane + i*32;
        if (idx < OUT_DIM) s += expf(v[i] - mx);
    }
    #pragma unroll
    for (int o = 16; o > 0; o >>= 1)
        s += __shfl_xor_sync(0xffffffffu, s, o);
    float lse = mx + logf(s);
    #pragma unroll
    for (int i = 0; i < 5; i++) {
        int idx = lane + i*32;
        if (idx < OUT_DIM) p[idx] = v[i] - lse;
    }
}

// -------------------- driver --------------------
extern "C" void kernel_launch(void* const* d_in, const int* in_sizes, int n_in,
                              void* d_out, int out_size) {
    const float* X     = (const float*)d_in[0];
    const float* Y     = (const float*)d_in[1];
    const float* eWih0 = (const float*)d_in[2];
    const float* eWhh0 = (const float*)d_in[3];
    const float* ebih0 = (const float*)d_in[4];
    const float* ebhh0 = (const float*)d_in[5];
    const float* eWih1 = (const float*)d_in[6];
    const float* eWhh1 = (const float*)d_in[7];
    const float* ebih1 = (const float*)d_in[8];
    const float* ebhh1 = (const float*)d_in[9];
    const float* dWih0 = (const float*)d_in[10];
    const float* dWhh0 = (const float*)d_in[11];
    const float* dbih0 = (const float*)d_in[12];
    const float* dbhh0 = (const float*)d_in[13];
    const float* dWih1 = (const float*)d_in[14];
    const float* dWhh1 = (const float*)d_in[15];
    const float* dbih1 = (const float*)d_in[16];
    const float* dbhh1 = (const float*)d_in[17];
    const float* lin_W = (const float*)d_in[18];
    const float* lin_b = (const float*)d_in[19];
    float* out = (float*)d_out;

    float *Zenc, *Zdec, *hn0, *hn1;
    __nv_bfloat16 *Hhi, *Hlo, *Xhi, *Xlo, *Dhi, *Dlo, *Wh, *Wl;
    cudaGetSymbolAddress((void**)&Zenc, g_Zenc);
    cudaGetSymbolAddress((void**)&Zdec, g_Zdec);
    cudaGetSymbolAddress((void**)&Hhi,  g_Hhi);
    cudaGetSymbolAddress((void**)&Hlo,  g_Hlo);
    cudaGetSymbolAddress((void**)&Xhi,  g_Xhi);
    cudaGetSymbolAddress((void**)&Xlo,  g_Xlo);
    cudaGetSymbolAddress((void**)&Dhi,  g_Dhi);
    cudaGetSymbolAddress((void**)&Dlo,  g_Dlo);
    cudaGetSymbolAddress((void**)&Wh,   g_Wh);
    cudaGetSymbolAddress((void**)&Wl,   g_Wl);
    cudaGetSymbolAddress((void**)&hn0,  g_hn0);
    cudaGetSymbolAddress((void**)&hn1,  g_hn1);

    cudaFuncSetAttribute((const void*)recur_kernel<4>,
                         cudaFuncAttributeMaxDynamicSharedMemorySize, RECUR_SMEM(4));
    cudaFuncSetAttribute((const void*)recur_kernel<8>,
                         cudaFuncAttributeMaxDynamicSharedMemorySize, RECUR_SMEM(8));
    cudaFuncSetAttribute((const void*)gemm_mma,
                         cudaFuncAttributeMaxDynamicSharedMemorySize, GM_SMEM);

    const int WSTRIDE = 256*256;
    const dim3 gG(MROWS/128, 2);   // 128x128 tiles; N=256 (or 131 masked)

    // weight splits
    wsplit<<<(256*KP_IN+255)/256, 256>>>(eWih0, Wh+0*WSTRIDE, Wl+0*WSTRIDE, HID, IN_DIM, KP_IN);
    wsplit<<<(256*KP_IN+255)/256, 256>>>(dWih0, Wh+1*WSTRIDE, Wl+1*WSTRIDE, HID, IN_DIM, KP_IN);
    wsplit<<<(256*256+255)/256, 256>>>(eWih1, Wh+2*WSTRIDE, Wl+2*WSTRIDE, HID, HID, 256);
    wsplit<<<(256*256+255)/256, 256>>>(dWih1, Wh+3*WSTRIDE, Wl+3*WSTRIDE, HID, HID, 256);
    wsplit<<<(256*256+255)/256, 256>>>(lin_W, Wh+4*WSTRIDE, Wl+4*WSTRIDE, OUT_DIM, HID, 256);
    // input splits
    xsplit<<<4096, 256>>>(X, Xhi, Xlo);
    decsplit<<<4096, 256>>>(X, Y, Dhi, Dlo);

    // Z_enc0 = X[:-1] @ eWih0^T + biases
    gemm_mma<<<gG, 256, GM_SMEM>>>(Xhi, Xlo, Wh+0*WSTRIDE, Wl+0*WSTRIDE,
                                   ebih0, ebhh0, Zenc, 256, KP_IN);
    // Z_dec0 = dec_in @ dWih0^T + biases
    gemm_mma<<<gG, 256, GM_SMEM>>>(Dhi, Dlo, Wh+1*WSTRIDE, Wl+1*WSTRIDE,
                                   dbih0, dbhh0, Zdec, 256, KP_IN);
    // encoder layer0 recurrence -> H (bf16 split), hn0
    {
        RArgs a; a.Z = Zenc; a.outHi = Hhi; a.outLo = Hlo; a.W = eWhh0; a.hInit = nullptr; a.hFinal = hn0;
        recur_kernel<4><<<128, 256, RECUR_SMEM(4)>>>(a, a, 64);
    }
    // Z_enc1 = out0 @ eWih1^T + biases
    gemm_mma<<<gG, 256, GM_SMEM>>>(Hhi, Hlo, Wh+2*WSTRIDE, Wl+2*WSTRIDE,
                                   ebih1, ebhh1, Zenc, 256, 256);
    // encoder layer1 (-> hn1) and decoder layer0 (-> H) concurrently
    {
        RArgs a0; a0.Z = Zenc; a0.outHi = nullptr; a0.outLo = nullptr; a0.W = eWhh1; a0.hInit = nullptr; a0.hFinal = hn1;
        RArgs a1; a1.Z = Zdec; a1.outHi = Hhi;     a1.outLo = Hlo;     a1.W = dWhh0; a1.hInit = hn0;     a1.hFinal = nullptr;
        recur_kernel<8><<<128, 256, RECUR_SMEM(8)>>>(a0, a1, 32);
    }
    // Z_dec1 = out_d0 @ dWih1^T + biases
    gemm_mma<<<gG, 256, GM_SMEM>>>(Hhi, Hlo, Wh+3*WSTRIDE, Wl+3*WSTRIDE,
                                   dbih1, dbhh1, Zdec, 256, 256);
    // decoder layer1 recurrence -> H
    {
        RArgs a; a.Z = Zdec; a.outHi = Hhi; a.outLo = Hlo; a.W = dWhh1; a.hInit = hn1; a.hFinal = nullptr;
        recur_kernel<4><<<128, 256, RECUR_SMEM(4)>>>(a, a, 64);
    }
    // logits = out_d1 @ lin_W^T + lin_b -> d_out (masked to 131 cols)
    gemm_mma<<<gG, 256, GM_SMEM>>>(Hhi, Hlo, Wh+4*WSTRIDE, Wl+4*WSTRIDE,
                                   lin_b, nullptr, out, OUT_DIM, 256);
    // log_softmax in place
    logsoftmax_kernel<<<(MROWS + 7)/8, 256>>>(out, MROWS);
}